// round 13
// baseline (speedup 1.0000x reference)
#include <cuda_runtime.h>
#include <cuda_bf16.h>
typedef unsigned int u32;
typedef unsigned long long u64;

#define NUM_SEQS 8
#define QLEN 128
#define NQH 32
#define NKVH 8
#define HDIM 128
#define MAXBLOCKS 128
#define NTHR 128
#define SCALE_F 0.08838834764831845f   // 1/sqrt(128)

// 8 KB fragment chunk per (physical block, kv head), K and V separately.
__device__ __align__(16) unsigned char g_kfrag[(size_t)8192 * 8192];  // 64 MB
__device__ __align__(16) unsigned char g_vfrag[(size_t)8192 * 8192];  // 64 MB

// ---- smem: three 32KB staging buffers + 16KB Q-lo fragment store ----
#define KOFF 0
#define VOFF 16384
#define SBUF 32768
#define QLOFF 98304
#define SMEM_BYTES 114688

// odd Taylor coeffs of 30*tanh(s/30) as poly in u=s^2:  scv = s*P(u)
#define TA0  1.0f
#define TA1 -3.7037037e-4f
#define TA2  1.6460905e-7f
#define TA3 -7.4015300e-11f
#define TA4  3.3330500e-14f
#define TA5 -1.5009900e-17f
#define TA6  6.7599000e-21f

__device__ __forceinline__ void bsplit(float x, float y, u32& hi, u32& lo){
    __nv_bfloat162 h = __floats2bfloat162_rn(x, y);
    float hx = __low2float(h), hy = __high2float(h);
    __nv_bfloat162 l = __floats2bfloat162_rn(x - hx, y - hy);
    hi = *reinterpret_cast<u32*>(&h);
    lo = *reinterpret_cast<u32*>(&l);
}
__device__ __forceinline__ void mma16816(float* c, const u32* a, u32 b0, u32 b1){
    asm volatile(
        "mma.sync.aligned.m16n8k16.row.col.f32.bf16.bf16.f32 "
        "{%0,%1,%2,%3},{%4,%5,%6,%7},{%8,%9},{%0,%1,%2,%3};"
        : "+f"(c[0]), "+f"(c[1]), "+f"(c[2]), "+f"(c[3])
        : "r"(a[0]), "r"(a[1]), "r"(a[2]), "r"(a[3]), "r"(b0), "r"(b1));
}
__device__ __forceinline__ u32 smem_u32(const void* p){
    u32 a; asm("{ .reg .u64 t; cvta.to.shared.u64 t, %1; cvt.u32.u64 %0, t; }":"=r"(a):"l"(p));
    return a;
}
#define CPA16(d, s) asm volatile("cp.async.cg.shared.global [%0], [%1], 16;"::"r"(d),"l"(s))
#define CPA_COMMIT() asm volatile("cp.async.commit_group;" ::: "memory")
#define CPA_WAIT(n)  asm volatile("cp.async.wait_group %0;" :: "n"(n) : "memory")

// =============== pre-pass: fp32 paged KV -> bf16 hi/lo fragment chunks ======
__global__ void __launch_bounds__(256, 4) convert_kv_kernel(
    const float* __restrict__ kc, const float* __restrict__ vc)
{
    const int b = blockIdx.x;              // b = pb*8 + hkv
    const int tid = threadIdx.x;
    const float* kb = kc + (size_t)b * 2048;
    const float* vb = vc + (size_t)b * 2048;
    unsigned char* kd = g_kfrag + ((size_t)b << 13);
    unsigned char* vd = g_vfrag + ((size_t)b << 13);

    #pragma unroll
    for (int it = 0; it < 2; it++){
        int lb = tid & 15;
        int f  = it*16 + (tid >> 4);       // 0..31
        int ks = f >> 2, qq = f & 3;
        int d0 = ks*16 + 2*qq;
        float x0 = kb[(d0+0)*16 + lb], x1 = kb[(d0+1)*16 + lb];
        float x2 = kb[(d0+8)*16 + lb], x3 = kb[(d0+9)*16 + lb];
        u32 b0h,b0l,b1h,b1l; bsplit(x0,x1,b0h,b0l); bsplit(x2,x3,b1h,b1l);
        int ntl = lb >> 3, fl = (lb&7)*4 + qq;
        *reinterpret_cast<uint4*>(kd + ((ntl*8 + ks)*32 + fl)*16)
            = make_uint4(b0h, b1h, b0l, b1l);
    }
    #pragma unroll
    for (int it = 0; it < 2; it++){
        int idx = it*256 + tid;            // 0..511
        int dv = idx >> 2, qq = idx & 3;
        const float* vr = vb + dv*16;
        float2 x01 = *reinterpret_cast<const float2*>(vr + 2*qq);
        float2 x89 = *reinterpret_cast<const float2*>(vr + 2*qq + 8);
        u32 b0h,b0l,b1h,b1l; bsplit(x01.x,x01.y,b0h,b0l); bsplit(x89.x,x89.y,b1h,b1l);
        int ntv = dv >> 3, fl = (dv&7)*4 + qq;
        *reinterpret_cast<uint4*>(vd + (ntv*32 + fl)*16)
            = make_uint4(b0h, b1h, b0l, b1l);
    }
}

// =============== main attention kernel ======================================
extern __shared__ char smem[];

// stage = 2 paged blocks (32 keys): copy 2x 8KB K + 2x 8KB V chunks.
__device__ __forceinline__ void issue_stage(u32 smb, const int* btp, int hkv, int tid){
    size_t c0 = ((size_t)(btp[0]*8 + hkv)) << 13;
    size_t c1 = ((size_t)(btp[1]*8 + hkv)) << 13;
    size_t srcs[2] = {c0, c1};
    #pragma unroll
    for (int it = 0; it < 8; it++){
        int idx = it*NTHR + tid;           // 0..1023
        int j = idx >> 9, off = (idx & 511) * 16;
        CPA16(smb + KOFF + j*8192 + off, g_kfrag + srcs[j] + off);
    }
    #pragma unroll
    for (int it = 0; it < 8; it++){
        int idx = it*NTHR + tid;
        int j = idx >> 9, off = (idx & 511) * 16;
        CPA16(smb + VOFF + j*8192 + off, g_vfrag + srcs[j] + off);
    }
}

__global__ void __launch_bounds__(NTHR, 2) Model_3470333575380_kernel(
    const float* __restrict__ query, const int* __restrict__ block_tables,
    const int* __restrict__ seq_lens, float* __restrict__ out)
{
    const int tid  = threadIdx.x;
    const int lane = tid & 31;
    const int w    = tid >> 5;       // 4 warps; warp owns q rows w*16..w*16+15
    const int g    = lane >> 2;
    const int qq   = lane & 3;

    const int cta = blockIdx.x;
    const int sp  = cta & 1;                    // segment pair
    const int qt  = (cta >> 1) & 1;             // q half (64 rows)
    const int h   = (cta >> 2) & (NQH - 1);
    const int s   = cta >> 7;
    const int hkv = h >> 2;

    const int seq_len = seq_lens[s];
    const int ctx = seq_len - QLEN;
    const int qa0 = ctx + qt*64 + w*16 + g;
    const int qa1 = qa0 + 8;

    const u32 smb = smem_u32(smem);
    const int* btbase = block_tables + s*MAXBLOCKS + sp*64;

    // prologue: prefetch stages 0 and 1 into buffers 0,1
    issue_stage(smb,        btbase,     hkv, tid); CPA_COMMIT();
    issue_stage(smb + SBUF, btbase + 2, hkv, tid); CPA_COMMIT();

    // ---- Q fragments: hi in registers, lo parked in smem (per-lane slot) ----
    u32 qh[8][4];
    {
        const float* q0 = query + ((size_t)(s*QLEN + qt*64 + w*16 + g)*NQH + h)*HDIM;
        const float* q8 = q0 + (size_t)8*NQH*HDIM;
        #pragma unroll
        for (int ks = 0; ks < 8; ks++){
            int d0 = ks*16 + 2*qq;
            float2 x0 = *reinterpret_cast<const float2*>(q0 + d0);
            float2 x1 = *reinterpret_cast<const float2*>(q8 + d0);
            float2 x2 = *reinterpret_cast<const float2*>(q0 + d0 + 8);
            float2 x3 = *reinterpret_cast<const float2*>(q8 + d0 + 8);
            u32 l0,l1,l2,l3;
            bsplit(x0.x*SCALE_F, x0.y*SCALE_F, qh[ks][0], l0);
            bsplit(x1.x*SCALE_F, x1.y*SCALE_F, qh[ks][1], l1);
            bsplit(x2.x*SCALE_F, x2.y*SCALE_F, qh[ks][2], l2);
            bsplit(x3.x*SCALE_F, x3.y*SCALE_F, qh[ks][3], l3);
            *reinterpret_cast<uint4*>(smem + QLOFF + ((w*8 + ks)*32 + lane)*16)
                = make_uint4(l0, l1, l2, l3);   // same-thread round-trip, no sync
        }
    }

    float dacc[16][4];
    #pragma unroll
    for (int i = 0; i < 16; i++){ dacc[i][0]=0.f; dacc[i][1]=0.f; dacc[i][2]=0.f; dacc[i][3]=0.f; }
    float m0 = -1e30f, m1 = -1e30f;

    // QK of stage stq into dst (scores only)
    auto do_qk = [&](int stq, float (&dst)[4][4]){
        const char* buf = smem + (stq % 3)*SBUF;
        #pragma unroll
        for (int i = 0; i < 4; i++){ dst[i][0]=0.f; dst[i][1]=0.f; dst[i][2]=0.f; dst[i][3]=0.f; }
        #pragma unroll
        for (int ks = 0; ks < 8; ks++){
            uint4 ql4 = *reinterpret_cast<const uint4*>(
                smem + QLOFF + ((w*8 + ks)*32 + lane)*16);
            u32 qlr[4] = {ql4.x, ql4.y, ql4.z, ql4.w};
            #pragma unroll
            for (int nt = 0; nt < 4; nt++){
                uint4 kf = *reinterpret_cast<const uint4*>(
                    buf + KOFF + (nt >> 1)*8192 + (((nt & 1)*8 + ks)*32 + lane)*16);
                mma16816(dst[nt], qh[ks], kf.x, kf.y);
                mma16816(dst[nt], qlr,    kf.x, kf.y);
                mma16816(dst[nt], qh[ks], kf.z, kf.w);
            }
        }
    };

    // full stage body: cur holds scores(st); computes QK(st+1) into nxt early
    auto stage_body = [&](int st, float (&cur)[4][4], float (&nxt)[4][4]){
        CPA_WAIT(0);
        __syncthreads();
        if (st + 2 < 32){
            issue_stage(smb + ((st + 2) % 3)*SBUF, btbase + (st+2)*2, hkv, tid);
            CPA_COMMIT();
        }

        // queue next stage's QK on the tensor pipe before the scalar epilogue
        if (st + 1 < 32) do_qk(st + 1, nxt);

        // ---- epilogue(st): softcap poly + causal + p = exp(scv-30) ----
        const int lb = sp*1024 + st*32;
        #pragma unroll
        for (int nt = 0; nt < 4; nt++){
            #pragma unroll
            for (int e = 0; e < 4; e++){
                int lg  = lb + nt*8 + qq*2 + (e & 1);
                int row = (e < 2) ? qa0 : qa1;
                float sv = cur[nt][e];
                sv = fminf(fmaxf(sv, -18.0f), 18.0f);
                float u = sv * sv;
                float pl = TA6;
                pl = fmaf(u, pl, TA5);
                pl = fmaf(u, pl, TA4);
                pl = fmaf(u, pl, TA3);
                pl = fmaf(u, pl, TA2);
                pl = fmaf(u, pl, TA1);
                pl = fmaf(u, pl, TA0);
                float scv = sv * pl;                 // 30*tanh(s/30)
                bool ok = (lg <= row);
                float p = ok ? __expf(scv - 30.0f) : 0.0f;
                if (ok){ if (e < 2) m0 = fmaxf(m0, scv); else m1 = fmaxf(m1, scv); }
                cur[nt][e] = p;
            }
        }

        // ---- PV(st): D += P * V, 3-pass bf16 ----
        const char* bufc = smem + (st % 3)*SBUF;
        #pragma unroll
        for (int ksv = 0; ksv < 2; ksv++){
            u32 ph[4], pl2[4];
            const float* p0 = cur[2*ksv];
            const float* p1 = cur[2*ksv + 1];
            bsplit(p0[0], p0[1], ph[0], pl2[0]);
            bsplit(p0[2], p0[3], ph[1], pl2[1]);
            bsplit(p1[0], p1[1], ph[2], pl2[2]);
            bsplit(p1[2], p1[3], ph[3], pl2[3]);
            #pragma unroll
            for (int ntv = 0; ntv < 16; ntv++){
                uint4 vf = *reinterpret_cast<const uint4*>(
                    bufc + VOFF + ksv*8192 + (ntv*32 + lane)*16);
                mma16816(dacc[ntv], ph,  vf.x, vf.y);
                mma16816(dacc[ntv], pl2, vf.x, vf.y);
                mma16816(dacc[ntv], ph,  vf.z, vf.w);
            }
        }

        // ---- segment boundary: scale by exp(30 - m), write, reset ----
        if ((st & 15) == 15){
            float a0 = m0, a1 = m1;
            #pragma unroll
            for (int o = 1; o <= 2; o <<= 1){
                a0 = fmaxf(a0, __shfl_xor_sync(0xffffffffu, a0, o));
                a1 = fmaxf(a1, __shfl_xor_sync(0xffffffffu, a1, o));
            }
            float sc0 = (a0 > -100.0f) ? __expf(30.0f - a0) : 0.0f;
            float sc1 = (a1 > -100.0f) ? __expf(30.0f - a1) : 0.0f;
            const int seg = sp*2 + (st >> 4);
            const int t0 = s*QLEN + qt*64 + w*16 + g;
            float* o0 = out + (((size_t)t0*NQH + h)*4 + seg)*HDIM;
            float* o1 = o0 + (size_t)8*NQH*4*HDIM;
            #pragma unroll
            for (int nt = 0; nt < 16; nt++){
                int dv = nt*8 + qq*2;
                *reinterpret_cast<float2*>(o0 + dv) =
                    make_float2(dacc[nt][0]*sc0, dacc[nt][1]*sc0);
                *reinterpret_cast<float2*>(o1 + dv) =
                    make_float2(dacc[nt][2]*sc1, dacc[nt][3]*sc1);
                dacc[nt][0]=0.f; dacc[nt][1]=0.f; dacc[nt][2]=0.f; dacc[nt][3]=0.f;
            }
            m0 = -1e30f; m1 = -1e30f;
        }
    };

    float saccA[4][4], saccB[4][4];

    // prolog: buffer 0 ready -> QK(0)
    CPA_WAIT(1);
    __syncthreads();
    do_qk(0, saccA);

    #pragma unroll 1
    for (int sth = 0; sth < 16; sth++){
        stage_body(2*sth,     saccA, saccB);
        stage_body(2*sth + 1, saccB, saccA);
    }
}

extern "C" void kernel_launch(void* const* d_in, const int* in_sizes, int n_in,
                              void* d_out, int out_size) {
    (void)in_sizes; (void)n_in; (void)out_size;
    const float* query        = (const float*)d_in[0];
    const float* key_cache    = (const float*)d_in[1];
    const float* value_cache  = (const float*)d_in[2];
    const int*   block_tables = (const int*)d_in[3];
    const int*   seq_lens     = (const int*)d_in[4];
    float* out = (float*)d_out;

    convert_kv_kernel<<<8192, 256>>>(key_cache, value_cache);

    cudaFuncSetAttribute(Model_3470333575380_kernel,
                         cudaFuncAttributeMaxDynamicSharedMemorySize, SMEM_BYTES);
    Model_3470333575380_kernel<<<NUM_SEQS*NQH*2*2, NTHR, SMEM_BYTES>>>(
        query, block_tables, seq_lens, out);
}

// round 14
// speedup vs baseline: 1.1776x; 1.1776x over previous
#include <cuda_runtime.h>
#include <cuda_bf16.h>
#include <cuda_fp16.h>
typedef unsigned int u32;
typedef unsigned long long u64;

#define NUM_SEQS 8
#define QLEN 128
#define NQH 32
#define NKVH 8
#define HDIM 128
#define MAXBLOCKS 128
#define NTHR 128
#define SCALE_F 0.08838834764831845f   // 1/sqrt(128)

// Pre-converted fragment chunks per (physical block, kv head):
// K chunk: fp16, [ntl<2][ks<8][lane<32] x 8B            -> 4 KB
// V chunk: bf16 hi/lo, [ntv<16][lane<32] x 16B          -> 8 KB
__device__ __align__(16) unsigned char g_kfrag[(size_t)8192 * 4096];  // 32 MB
__device__ __align__(16) unsigned char g_vfrag[(size_t)8192 * 8192];  // 64 MB

// ---- smem: three 24KB staging buffers (K 8KB + V 16KB) ----
#define KOFF 0
#define VOFF 8192
#define SBUF 24576
#define SMEM_BYTES 73728

// odd Taylor coeffs of 30*tanh(s/30) as poly in u=s^2:  scv = s*P(u)
#define TA0  1.0f
#define TA1 -3.7037037e-4f
#define TA2  1.6460905e-7f
#define TA3 -7.4015300e-11f
#define TA4  3.3330500e-14f
#define TA5 -1.5009900e-17f
#define TA6  6.7599000e-21f

__device__ __forceinline__ void bsplit(float x, float y, u32& hi, u32& lo){
    __nv_bfloat162 h = __floats2bfloat162_rn(x, y);
    float hx = __low2float(h), hy = __high2float(h);
    __nv_bfloat162 l = __floats2bfloat162_rn(x - hx, y - hy);
    hi = *reinterpret_cast<u32*>(&h);
    lo = *reinterpret_cast<u32*>(&l);
}
__device__ __forceinline__ u32 hpack(float x, float y){
    __half2 h = __floats2half2_rn(x, y);
    return *reinterpret_cast<u32*>(&h);
}
// bf16 x bf16 -> f32
__device__ __forceinline__ void mma_bf16(float* c, const u32* a, u32 b0, u32 b1){
    asm volatile(
        "mma.sync.aligned.m16n8k16.row.col.f32.bf16.bf16.f32 "
        "{%0,%1,%2,%3},{%4,%5,%6,%7},{%8,%9},{%0,%1,%2,%3};"
        : "+f"(c[0]), "+f"(c[1]), "+f"(c[2]), "+f"(c[3])
        : "r"(a[0]), "r"(a[1]), "r"(a[2]), "r"(a[3]), "r"(b0), "r"(b1));
}
// fp16 x fp16 -> f32
__device__ __forceinline__ void mma_f16(float* c, const u32* a, u32 b0, u32 b1){
    asm volatile(
        "mma.sync.aligned.m16n8k16.row.col.f32.f16.f16.f32 "
        "{%0,%1,%2,%3},{%4,%5,%6,%7},{%8,%9},{%0,%1,%2,%3};"
        : "+f"(c[0]), "+f"(c[1]), "+f"(c[2]), "+f"(c[3])
        : "r"(a[0]), "r"(a[1]), "r"(a[2]), "r"(a[3]), "r"(b0), "r"(b1));
}
__device__ __forceinline__ u32 smem_u32(const void* p){
    u32 a; asm("{ .reg .u64 t; cvta.to.shared.u64 t, %1; cvt.u32.u64 %0, t; }":"=r"(a):"l"(p));
    return a;
}
#define CPA16(d, s) asm volatile("cp.async.cg.shared.global [%0], [%1], 16;"::"r"(d),"l"(s))
#define CPA_COMMIT() asm volatile("cp.async.commit_group;" ::: "memory")
#define CPA_WAIT(n)  asm volatile("cp.async.wait_group %0;" :: "n"(n) : "memory")

// =============== pre-pass: fp32 paged KV -> fragment chunks =================
__global__ void __launch_bounds__(256, 4) convert_kv_kernel(
    const float* __restrict__ kc, const float* __restrict__ vc)
{
    const int b = blockIdx.x;              // b = pb*8 + hkv
    const int tid = threadIdx.x;
    const float* kb = kc + (size_t)b * 2048;
    const float* vb = vc + (size_t)b * 2048;
    unsigned char* kd = g_kfrag + ((size_t)b << 12);
    unsigned char* vd = g_vfrag + ((size_t)b << 13);

    // K: 512 items = (lb<16, ks<8, qq<4) -> fp16 pairs, 8 B each
    #pragma unroll
    for (int it = 0; it < 2; it++){
        int lb = tid & 15;
        int f  = it*16 + (tid >> 4);       // 0..31
        int ks = f >> 2, qq = f & 3;
        int d0 = ks*16 + 2*qq;
        float x0 = kb[(d0+0)*16 + lb], x1 = kb[(d0+1)*16 + lb];
        float x2 = kb[(d0+8)*16 + lb], x3 = kb[(d0+9)*16 + lb];
        u32 b0 = hpack(x0, x1), b1 = hpack(x2, x3);
        int ntl = lb >> 3, fl = (lb&7)*4 + qq;
        *reinterpret_cast<uint2*>(kd + ((ntl*8 + ks)*32 + fl)*8)
            = make_uint2(b0, b1);
    }
    // V: 512 items = (dv<128, qq<4) -> bf16 hi/lo, 16 B each
    #pragma unroll
    for (int it = 0; it < 2; it++){
        int idx = it*256 + tid;            // 0..511
        int dv = idx >> 2, qq = idx & 3;
        const float* vr = vb + dv*16;
        float2 x01 = *reinterpret_cast<const float2*>(vr + 2*qq);
        float2 x89 = *reinterpret_cast<const float2*>(vr + 2*qq + 8);
        u32 b0h,b0l,b1h,b1l; bsplit(x01.x,x01.y,b0h,b0l); bsplit(x89.x,x89.y,b1h,b1l);
        int ntv = dv >> 3, fl = (dv&7)*4 + qq;
        *reinterpret_cast<uint4*>(vd + (ntv*32 + fl)*16)
            = make_uint4(b0h, b1h, b0l, b1l);
    }
}

// =============== main attention kernel ======================================
extern __shared__ char smem[];

// stage = 2 paged blocks (32 keys): 2x 4KB K + 2x 8KB V chunks.
__device__ __forceinline__ void issue_stage(u32 smb, const int* btp, int hkv, int tid){
    size_t kc0 = ((size_t)(btp[0]*8 + hkv)) << 12;
    size_t kc1 = ((size_t)(btp[1]*8 + hkv)) << 12;
    size_t vc0 = ((size_t)(btp[0]*8 + hkv)) << 13;
    size_t vc1 = ((size_t)(btp[1]*8 + hkv)) << 13;
    size_t ksrc[2] = {kc0, kc1};
    size_t vsrc[2] = {vc0, vc1};
    #pragma unroll
    for (int it = 0; it < 4; it++){
        int idx = it*NTHR + tid;           // 0..511
        int j = idx >> 8, off = (idx & 255) * 16;
        CPA16(smb + KOFF + j*4096 + off, g_kfrag + ksrc[j] + off);
    }
    #pragma unroll
    for (int it = 0; it < 8; it++){
        int idx = it*NTHR + tid;           // 0..1023
        int j = idx >> 9, off = (idx & 511) * 16;
        CPA16(smb + VOFF + j*8192 + off, g_vfrag + vsrc[j] + off);
    }
}

__global__ void __launch_bounds__(NTHR, 2) Model_3470333575380_kernel(
    const float* __restrict__ query, const int* __restrict__ block_tables,
    const int* __restrict__ seq_lens, float* __restrict__ out)
{
    const int tid  = threadIdx.x;
    const int lane = tid & 31;
    const int w    = tid >> 5;       // 4 warps; warp owns q rows w*16..w*16+15
    const int g    = lane >> 2;
    const int qq   = lane & 3;

    const int cta = blockIdx.x;
    const int sp  = cta & 1;                    // segment pair
    const int qt  = (cta >> 1) & 1;             // q half (64 rows)
    const int h   = (cta >> 2) & (NQH - 1);
    const int s   = cta >> 7;
    const int hkv = h >> 2;

    const int seq_len = seq_lens[s];
    const int ctx = seq_len - QLEN;
    const int qa0 = ctx + qt*64 + w*16 + g;
    const int qa1 = qa0 + 8;

    const u32 smb = smem_u32(smem);
    const int* btbase = block_tables + s*MAXBLOCKS + sp*64;

    // prologue: prefetch stages 0 and 1 into buffers 0,1
    issue_stage(smb,        btbase,     hkv, tid); CPA_COMMIT();
    issue_stage(smb + SBUF, btbase + 2, hkv, tid); CPA_COMMIT();

    // ---- Q fragments (fp16, pre-scaled) in registers ----
    u32 qf[8][4];
    {
        const float* q0 = query + ((size_t)(s*QLEN + qt*64 + w*16 + g)*NQH + h)*HDIM;
        const float* q8 = q0 + (size_t)8*NQH*HDIM;
        #pragma unroll
        for (int ks = 0; ks < 8; ks++){
            int d0 = ks*16 + 2*qq;
            float2 x0 = *reinterpret_cast<const float2*>(q0 + d0);
            float2 x1 = *reinterpret_cast<const float2*>(q8 + d0);
            float2 x2 = *reinterpret_cast<const float2*>(q0 + d0 + 8);
            float2 x3 = *reinterpret_cast<const float2*>(q8 + d0 + 8);
            qf[ks][0] = hpack(x0.x*SCALE_F, x0.y*SCALE_F);
            qf[ks][1] = hpack(x1.x*SCALE_F, x1.y*SCALE_F);
            qf[ks][2] = hpack(x2.x*SCALE_F, x2.y*SCALE_F);
            qf[ks][3] = hpack(x3.x*SCALE_F, x3.y*SCALE_F);
        }
    }

    float dacc[16][4];
    #pragma unroll
    for (int i = 0; i < 16; i++){ dacc[i][0]=0.f; dacc[i][1]=0.f; dacc[i][2]=0.f; dacc[i][3]=0.f; }
    float m0 = -1e30f, m1 = -1e30f;

    int bufi = 0;                                // st % 3
    #pragma unroll 1
    for (int st = 0; st < 32; st++){
        // wait for stage st's staging group, then one barrier for visibility
        if (st < 31) { CPA_WAIT(1); } else { CPA_WAIT(0); }
        __syncthreads();

        // issue prefetch of stage st+2 (overlaps entire stage compute)
        if (st + 2 < 32){
            int nb = bufi + 2; if (nb >= 3) nb -= 3;
            issue_stage(smb + nb*SBUF, btbase + (st+2)*2, hkv, tid);
            CPA_COMMIT();
        }

        const char* bufc = smem + bufi*SBUF;
        const int lb = sp*1024 + st*32;

        // ---- QK: S[16 x 32] per warp, single-pass fp16, 1 LDS.64 per tile ----
        float sacc[4][4];
        #pragma unroll
        for (int i = 0; i < 4; i++){ sacc[i][0]=0.f; sacc[i][1]=0.f; sacc[i][2]=0.f; sacc[i][3]=0.f; }
        #pragma unroll
        for (int ks = 0; ks < 8; ks++){
            #pragma unroll
            for (int nt = 0; nt < 4; nt++){     // nt = j*2 + ntl
                uint2 kf = *reinterpret_cast<const uint2*>(
                    bufc + KOFF + (nt >> 1)*4096 + (((nt & 1)*8 + ks)*32 + lane)*8);
                mma_f16(sacc[nt], qf[ks], kf.x, kf.y);
            }
        }

        // ---- softcap via odd poly of tanh + causal + p = exp(scv-30) ----
        #pragma unroll
        for (int nt = 0; nt < 4; nt++){
            #pragma unroll
            for (int e = 0; e < 4; e++){
                int lg  = lb + nt*8 + qq*2 + (e & 1);
                int row = (e < 2) ? qa0 : qa1;
                float sv = sacc[nt][e];
                sv = fminf(fmaxf(sv, -18.0f), 18.0f);
                float u = sv * sv;
                float pl = TA6;
                pl = fmaf(u, pl, TA5);
                pl = fmaf(u, pl, TA4);
                pl = fmaf(u, pl, TA3);
                pl = fmaf(u, pl, TA2);
                pl = fmaf(u, pl, TA1);
                pl = fmaf(u, pl, TA0);
                float scv = sv * pl;                 // 30*tanh(s/30)
                bool ok = (lg <= row);
                float p = ok ? __expf(scv - 30.0f) : 0.0f;
                if (ok){ if (e < 2) m0 = fmaxf(m0, scv); else m1 = fmaxf(m1, scv); }
                sacc[nt][e] = p;
            }
        }

        // ---- PV: D[16 x 128] += P * V, 3-pass bf16 ----
        #pragma unroll
        for (int ksv = 0; ksv < 2; ksv++){      // ksv = paged block j
            u32 ph[4], pl2[4];
            const float* p0 = sacc[2*ksv];
            const float* p1 = sacc[2*ksv + 1];
            bsplit(p0[0], p0[1], ph[0], pl2[0]);
            bsplit(p0[2], p0[3], ph[1], pl2[1]);
            bsplit(p1[0], p1[1], ph[2], pl2[2]);
            bsplit(p1[2], p1[3], ph[3], pl2[3]);
            #pragma unroll
            for (int ntv = 0; ntv < 16; ntv++){
                uint4 vf = *reinterpret_cast<const uint4*>(
                    bufc + VOFF + ksv*8192 + (ntv*32 + lane)*16);
                mma_bf16(dacc[ntv], ph,  vf.x, vf.y);
                mma_bf16(dacc[ntv], pl2, vf.x, vf.y);
                mma_bf16(dacc[ntv], ph,  vf.z, vf.w);
            }
        }

        // ---- segment boundary: scale by exp(30 - m), write, reset ----
        if ((st & 15) == 15){
            float a0 = m0, a1 = m1;
            #pragma unroll
            for (int o = 1; o <= 2; o <<= 1){
                a0 = fmaxf(a0, __shfl_xor_sync(0xffffffffu, a0, o));
                a1 = fmaxf(a1, __shfl_xor_sync(0xffffffffu, a1, o));
            }
            float sc0 = (a0 > -100.0f) ? __expf(30.0f - a0) : 0.0f;
            float sc1 = (a1 > -100.0f) ? __expf(30.0f - a1) : 0.0f;
            const int seg = sp*2 + (st >> 4);
            const int t0 = s*QLEN + qt*64 + w*16 + g;
            float* o0 = out + (((size_t)t0*NQH + h)*4 + seg)*HDIM;
            float* o1 = o0 + (size_t)8*NQH*4*HDIM;
            #pragma unroll
            for (int nt = 0; nt < 16; nt++){
                int dv = nt*8 + qq*2;
                *reinterpret_cast<float2*>(o0 + dv) =
                    make_float2(dacc[nt][0]*sc0, dacc[nt][1]*sc0);
                *reinterpret_cast<float2*>(o1 + dv) =
                    make_float2(dacc[nt][2]*sc1, dacc[nt][3]*sc1);
                dacc[nt][0]=0.f; dacc[nt][1]=0.f; dacc[nt][2]=0.f; dacc[nt][3]=0.f;
            }
            m0 = -1e30f; m1 = -1e30f;
        }

        bufi++; if (bufi == 3) bufi = 0;
    }
}

extern "C" void kernel_launch(void* const* d_in, const int* in_sizes, int n_in,
                              void* d_out, int out_size) {
    (void)in_sizes; (void)n_in; (void)out_size;
    const float* query        = (const float*)d_in[0];
    const float* key_cache    = (const float*)d_in[1];
    const float* value_cache  = (const float*)d_in[2];
    const int*   block_tables = (const int*)d_in[3];
    const int*   seq_lens     = (const int*)d_in[4];
    float* out = (float*)d_out;

    convert_kv_kernel<<<8192, 256>>>(key_cache, value_cache);

    cudaFuncSetAttribute(Model_3470333575380_kernel,
                         cudaFuncAttributeMaxDynamicSharedMemorySize, SMEM_BYTES);
    Model_3470333575380_kernel<<<NUM_SEQS*NQH*2*2, NTHR, SMEM_BYTES>>>(
        query, block_tables, seq_lens, out);
}